// round 9
// baseline (speedup 1.0000x reference)
#include <cuda_runtime.h>
#include <cuda_bf16.h>
#include <cstdint>

typedef unsigned long long ULL;
typedef __nv_bfloat16 bf16;

#define NTOK 1024
#define CQ   768
#define CZ   128
#define NH   16
#define HD   48
#define HDQ  768
#define QSCALE 0.14433756729740643f  // 1/sqrt(48)

// ================= f32x2 helpers (pair_bias) =================
__device__ __forceinline__ ULL fma2(ULL a, ULL b, ULL c) {
    ULL d; asm("fma.rn.f32x2 %0, %1, %2, %3;" : "=l"(d) : "l"(a), "l"(b), "l"(c)); return d;
}
__device__ __forceinline__ ULL add2(ULL a, ULL b) {
    ULL d; asm("add.rn.f32x2 %0, %1, %2;" : "=l"(d) : "l"(a), "l"(b)); return d;
}
__device__ __forceinline__ float lo2(ULL u){ return __uint_as_float((unsigned)u); }
__device__ __forceinline__ float hi2(ULL u){ return __uint_as_float((unsigned)(u >> 32)); }

// ================= mma.sync helpers =================
__device__ __forceinline__ uint32_t s2u(const void* p){
    uint32_t a; asm("{ .reg .u64 t; cvta.to.shared.u64 t, %1; cvt.u32.u64 %0, t; }" : "=r"(a) : "l"(p));
    return a;
}
__device__ __forceinline__ void ldsm4(uint32_t* r, uint32_t addr){
    asm volatile("ldmatrix.sync.aligned.m8n8.x4.shared.b16 {%0,%1,%2,%3}, [%4];"
        : "=r"(r[0]), "=r"(r[1]), "=r"(r[2]), "=r"(r[3]) : "r"(addr));
}
__device__ __forceinline__ void mma16816(float* c, uint32_t a0, uint32_t a1, uint32_t a2, uint32_t a3,
                                         uint32_t b0, uint32_t b1){
    asm volatile("mma.sync.aligned.m16n8k16.row.col.f32.bf16.bf16.f32 "
        "{%0,%1,%2,%3}, {%4,%5,%6,%7}, {%8,%9}, {%0,%1,%2,%3};"
        : "+f"(c[0]), "+f"(c[1]), "+f"(c[2]), "+f"(c[3])
        : "r"(a0), "r"(a1), "r"(a2), "r"(a3), "r"(b0), "r"(b1));
}
__device__ __forceinline__ void cpa16(uint32_t dst, const void* src, bool p){
    int sz = p ? 16 : 0;
    asm volatile("cp.async.cg.shared.global [%0], [%1], 16, %2;"
        :: "r"(dst), "l"(src), "r"(sz) : "memory");
}
#define CP_COMMIT() asm volatile("cp.async.commit_group;" ::: "memory")
#define CP_WAIT(N)  asm volatile("cp.async.wait_group %0;" :: "n"(N) : "memory")

// ================= scratch =================
__device__ float g_bias[(size_t)NH * NTOK * NTOK];
__device__ bf16  g_anh[NTOK * CQ], g_anl[NTOK * CQ];
__device__ bf16  g_wTh[5u * CQ * CQ], g_wTl[5u * CQ * CQ];   // [n][k]
__device__ bf16  g_qh[NH * NTOK * HD], g_ql[NH * NTOK * HD];
__device__ bf16  g_kh[NH * NTOK * HD], g_kl[NH * NTOK * HD];
__device__ bf16  g_vth[NH * HD * NTOK], g_vtl[NH * HD * NTOK]; // [h][d][tok]
__device__ bf16  g_ph[(size_t)NH * NTOK * NTOK], g_pl[(size_t)NH * NTOK * NTOK];
__device__ float g_gate[NTOK * HDQ];
__device__ bf16  g_ogh[NTOK * HDQ], g_ogl[NTOK * HDQ];

// ================= LayerNorm of a -> bf16 splits =================
__global__ void k_ln_a(const float* __restrict__ a, const float* __restrict__ g,
                       const float* __restrict__ b) {
    int row = blockIdx.x, tid = threadIdx.x;
    const float* x = a + (size_t)row * CQ;
    float v0 = x[tid], v1 = x[tid + 256], v2 = x[tid + 512];
    float s = v0 + v1 + v2;
    float ss = v0*v0 + v1*v1 + v2*v2;
    __shared__ float sred[8], sred2[8];
    #pragma unroll
    for (int o = 16; o; o >>= 1) {
        s  += __shfl_xor_sync(0xffffffffu, s, o);
        ss += __shfl_xor_sync(0xffffffffu, ss, o);
    }
    if ((tid & 31) == 0) { sred[tid >> 5] = s; sred2[tid >> 5] = ss; }
    __syncthreads();
    if (tid == 0) {
        float S = 0, SS = 0;
        for (int i = 0; i < 8; i++) { S += sred[i]; SS += sred2[i]; }
        float mu = S * (1.0f / CQ);
        float var = SS * (1.0f / CQ) - mu * mu;
        sred[0] = mu; sred2[0] = rsqrtf(var + 1e-5f);
    }
    __syncthreads();
    float mu = sred[0], rstd = sred2[0];
    #pragma unroll
    for (int j = 0; j < 3; j++) {
        int c = tid + j * 256;
        float v = (j == 0 ? v0 : j == 1 ? v1 : v2);
        float vn = (v - mu) * rstd * g[c] + b[c];
        bf16 h = __float2bfloat16(vn);
        g_anh[(size_t)row * CQ + c] = h;
        g_anl[(size_t)row * CQ + c] = __float2bfloat16(vn - __bfloat162float(h));
    }
}

// ================= weight transpose + split =================
__global__ void k_splitw(const float* w0, const float* w1, const float* w2,
                         const float* w3, const float* w4) {
    int which = blockIdx.y;
    const float* w = (which == 0) ? w0 : (which == 1) ? w1 : (which == 2) ? w2 :
                     (which == 3) ? w3 : w4;
    int idx = blockIdx.x * 256 + threadIdx.x;   // k*768 + n
    int k = idx / CQ, n = idx - k * CQ;
    float v = w[idx];
    bf16 h = __float2bfloat16(v);
    size_t off = (size_t)which * CQ * CQ + (size_t)n * CQ + k;
    g_wTh[off] = h;
    g_wTl[off] = __float2bfloat16(v - __bfloat162float(h));
}

// ================= pair bias (SIMT, DRAM-bound) =================
#define PB_SMEM_FLOATS (2*256*32 + 2048 + 32)
__global__ __launch_bounds__(256, 2)
void k_pair_bias(const float* __restrict__ z, const float* __restrict__ gz,
                 const float* __restrict__ bz, const float* __restrict__ wz) {
    extern __shared__ float sm[];
    float* zb    = sm;
    float* wps   = sm + 16384;
    float* cs_cb = wps + 2048;

    int tid = threadIdx.x;
    for (int i = tid; i < CZ * NH; i += 256) {
        int c = i >> 4, h = i & 15;
        wps[(c >> 1) * 32 + h * 2 + (c & 1)] = gz[c] * wz[c * NH + h];
    }
    __syncthreads();
    if (tid < 16) {
        float cs = 0.f, cb = 0.f;
        for (int c = 0; c < CZ; c++) {
            cs += wps[(c >> 1) * 32 + tid * 2 + (c & 1)];
            cb += bz[c] * wz[c * NH + tid];
        }
        cs_cb[tid] = cs; cs_cb[16 + tid] = cb;
    }
    __syncthreads();

    int tile = blockIdx.x;
    const float4* zg = (const float4*)(z + (size_t)tile * 256 * CZ);

    int srow[8], sf[8];
    #pragma unroll
    for (int j = 0; j < 8; j++) { int i = tid + j * 256; srow[j] = i >> 3; sf[j] = i & 7; }

    float4 pre[8];
    #pragma unroll
    for (int j = 0; j < 8; j++)
        pre[j] = zg[(size_t)srow[j] * 32 + sf[j]];

    ULL acc[NH];
    #pragma unroll
    for (int h = 0; h < NH; h++) acc[h] = 0ULL;
    ULL sum2 = 0ULL, ss2 = 0ULL;

    for (int c = 0; c < 4; c++) {
        float* buf = zb + (c & 1) * 8192;
        #pragma unroll
        for (int j = 0; j < 8; j++)
            *(float4*)(buf + srow[j] * 32 + ((sf[j] + srow[j]) & 7) * 4) = pre[j];
        __syncthreads();
        if (c < 3) {
            #pragma unroll
            for (int j = 0; j < 8; j++)
                pre[j] = zg[(size_t)srow[j] * 32 + (c + 1) * 8 + sf[j]];
        }
        #pragma unroll
        for (int j = 0; j < 8; j++) {
            int pos = (j + tid) & 7;
            float4 zv = *(const float4*)(buf + tid * 32 + pos * 4);
            ULL z01 = ((const ULL*)&zv)[0];
            ULL z23 = ((const ULL*)&zv)[1];
            sum2 = add2(sum2, add2(z01, z23));
            ss2  = fma2(z01, z01, fma2(z23, z23, ss2));
            int p0 = c * 16 + 2 * j;
            const float4* w0 = (const float4*)(wps + p0 * 32);
            const float4* w1 = (const float4*)(wps + p0 * 32 + 32);
            #pragma unroll
            for (int h2 = 0; h2 < 8; h2++) {
                float4 wa = w0[h2];
                float4 wb = w1[h2];
                acc[2*h2]     = fma2(z01, ((const ULL*)&wa)[0], acc[2*h2]);
                acc[2*h2 + 1] = fma2(z01, ((const ULL*)&wa)[1], acc[2*h2 + 1]);
                acc[2*h2]     = fma2(z23, ((const ULL*)&wb)[0], acc[2*h2]);
                acc[2*h2 + 1] = fma2(z23, ((const ULL*)&wb)[1], acc[2*h2 + 1]);
            }
        }
        __syncthreads();
    }

    float sum = lo2(sum2) + hi2(sum2);
    float ss  = lo2(ss2)  + hi2(ss2);
    float mu  = sum * (1.0f / CZ);
    float var = ss * (1.0f / CZ) - mu * mu;
    float rstd = rsqrtf(var + 1e-5f);

    float* outs = zb;
    #pragma unroll
    for (int h = 0; h < NH; h++) {
        float d = lo2(acc[h]) + hi2(acc[h]);
        outs[h * 256 + tid] = rstd * (d - mu * cs_cb[h]) + cs_cb[16 + h];
    }
    __syncthreads();
    #pragma unroll
    for (int it = 0; it < 4; it++) {
        int idx = tid + it * 256;
        int h = idx >> 6, j4 = idx & 63;
        float4 v = *(const float4*)(outs + h * 256 + j4 * 4);
        *(float4*)(g_bias + ((size_t)h << 20) + (size_t)tile * 256 + j4 * 4) = v;
    }
}

// ================= bf16x3 mma.sync GEMM core, 2-stage cp.async pipeline =================
#define ASTR 40
// stage layout (bytes): Ah 0 (10240), Al 10240 (10240), Bh 20480 (5120), Bl 25600 (5120)
#define ST_AL 10240u
#define ST_BH 20480u
#define ST_BL 25600u
#define STAGE_BYTES 30720u
#define GEMM_SMEM (2 * STAGE_BYTES)

__device__ __forceinline__ void stage_chunk(
    const bf16* __restrict__ Ah, const bf16* __restrict__ Al, int lda,
    const bf16* __restrict__ Bh, const bf16* __restrict__ Bl, int ldb, int nrealB,
    int k0, int Kreal, uint32_t sb)
{
    int tid = threadIdx.x;
    #pragma unroll
    for (int j = 0; j < 2; j++) {
        int i = tid + j * 256;                 // < 512
        int r = i >> 2, g = i & 3, k = k0 + g * 8;
        bool p = (k < Kreal);
        const bf16* sa = p ? (Ah + (size_t)r * lda + k) : Ah;
        const bf16* sl = p ? (Al + (size_t)r * lda + k) : Al;
        uint32_t doff = (uint32_t)(r * ASTR + g * 8) * 2;
        cpa16(sb + doff, sa, p);
        cpa16(sb + ST_AL + doff, sl, p);
    }
    {
        int r = tid >> 2, g = tid & 3, k = k0 + g * 8;
        bool p = (r < nrealB) && (k < Kreal);
        const bf16* sbh = p ? (Bh + (size_t)r * ldb + k) : Bh;
        const bf16* sbl = p ? (Bl + (size_t)r * ldb + k) : Bl;
        uint32_t doff = (uint32_t)(r * ASTR + g * 8) * 2;
        cpa16(sb + ST_BH + doff, sbh, p);
        cpa16(sb + ST_BL + doff, sbl, p);
    }
    CP_COMMIT();
}

__device__ __forceinline__ void gemm_core(
    const bf16* __restrict__ Ah, const bf16* __restrict__ Al, int lda,
    const bf16* __restrict__ Bh, const bf16* __restrict__ Bl, int ldb, int nrealB,
    int Kreal, int nchunks, uint32_t sbase, float acc[2][4][4])
{
    int lane = threadIdx.x & 31, wid = threadIdx.x >> 5;
    int wm = wid & 3, wn = wid >> 2;
    #pragma unroll
    for (int f = 0; f < 2; f++)
        #pragma unroll
        for (int nf = 0; nf < 4; nf++)
            #pragma unroll
            for (int i = 0; i < 4; i++) acc[f][nf][i] = 0.f;

    int sub = lane >> 3, rin = lane & 7;
    int rowoff = ((sub & 1) << 3) + rin;
    int koff = (sub >> 1) << 3;

    stage_chunk(Ah, Al, lda, Bh, Bl, ldb, nrealB, 0, Kreal, sbase);

    for (int c = 0; c < nchunks; c++) {
        uint32_t sb = sbase + (uint32_t)(c & 1) * STAGE_BYTES;
        if (c + 1 < nchunks) {
            stage_chunk(Ah, Al, lda, Bh, Bl, ldb, nrealB, (c + 1) * 32, Kreal,
                        sbase + (uint32_t)((c + 1) & 1) * STAGE_BYTES);
            CP_WAIT(1);
        } else {
            CP_WAIT(0);
        }
        __syncthreads();

        #pragma unroll
        for (int s = 0; s < 2; s++) {
            uint32_t ah[2][4], al[2][4], bh[2][4], bl[2][4];
            #pragma unroll
            for (int f = 0; f < 2; f++) {
                uint32_t off = (uint32_t)((wm * 32 + f * 16 + rowoff) * ASTR + s * 16 + koff) * 2;
                ldsm4(ah[f], sb + off);
                ldsm4(al[f], sb + ST_AL + off);
            }
            #pragma unroll
            for (int g2 = 0; g2 < 2; g2++) {
                uint32_t off = (uint32_t)((wn * 32 + g2 * 16 + rowoff) * ASTR + s * 16 + koff) * 2;
                ldsm4(bh[g2], sb + ST_BH + off);
                ldsm4(bl[g2], sb + ST_BL + off);
            }
            #pragma unroll
            for (int f = 0; f < 2; f++)
                #pragma unroll
                for (int nf = 0; nf < 4; nf++) {
                    int g2 = nf >> 1, o = nf & 1;
                    mma16816(acc[f][nf], ah[f][0], ah[f][1], ah[f][2], ah[f][3],
                             bh[g2][o], bh[g2][2 + o]);
                    mma16816(acc[f][nf], ah[f][0], ah[f][1], ah[f][2], ah[f][3],
                             bl[g2][o], bl[g2][2 + o]);
                    mma16816(acc[f][nf], al[f][0], al[f][1], al[f][2], al[f][3],
                             bh[g2][o], bh[g2][2 + o]);
                }
        }
        __syncthreads();
    }
}

#define GEMM_SHARED \
    extern __shared__ char dsm[]; \
    uint32_t sbase = s2u(dsm); \
    float acc[2][4][4]; \
    int lane = threadIdx.x & 31, wid = threadIdx.x >> 5; \
    int wm = wid & 3, wn = wid >> 2; \
    int erow = wm * 32 + (lane >> 2); \
    int ecol = wn * 32 + (lane & 3) * 2;

// ---- QKVG ----
__global__ __launch_bounds__(256)
void k_gemm_qkvg(const float* __restrict__ bg) {
    GEMM_SHARED;
    int mode = blockIdx.z;
    int row0 = blockIdx.y * 128, n0 = blockIdx.x * 64;
    const bf16* Bh = g_wTh + (size_t)mode * CQ * CQ + (size_t)n0 * CQ;
    const bf16* Bl = g_wTl + (size_t)mode * CQ * CQ + (size_t)n0 * CQ;
    gemm_core(g_anh + (size_t)row0 * CQ, g_anl + (size_t)row0 * CQ, CQ,
              Bh, Bl, CQ, 64, CQ, CQ / 32, sbase, acc);
    #pragma unroll
    for (int f = 0; f < 2; f++)
        #pragma unroll
        for (int nf = 0; nf < 4; nf++)
            #pragma unroll
            for (int i = 0; i < 4; i++) {
                int row = row0 + erow + f * 16 + (i >> 1) * 8;
                int col = n0 + ecol + nf * 8 + (i & 1);
                float v = acc[f][nf][i];
                int h = col / HD, d = col - h * HD;
                if (mode == 0) {
                    float q = v * QSCALE;
                    bf16 hh = __float2bfloat16(q);
                    g_qh[((size_t)h * NTOK + row) * HD + d] = hh;
                    g_ql[((size_t)h * NTOK + row) * HD + d] = __float2bfloat16(q - __bfloat162float(hh));
                } else if (mode == 1) {
                    bf16 hh = __float2bfloat16(v);
                    g_kh[((size_t)h * NTOK + row) * HD + d] = hh;
                    g_kl[((size_t)h * NTOK + row) * HD + d] = __float2bfloat16(v - __bfloat162float(hh));
                } else if (mode == 2) {
                    bf16 hh = __float2bfloat16(v);
                    g_vth[((size_t)h * HD + d) * NTOK + row] = hh;
                    g_vtl[((size_t)h * HD + d) * NTOK + row] = __float2bfloat16(v - __bfloat162float(hh));
                } else {
                    g_gate[(size_t)row * HDQ + col] = 1.f / (1.f + __expf(-(v + bg[col])));
                }
            }
}

// ---- scores ----
__global__ __launch_bounds__(256)
void k_gemm_scores(const float* __restrict__ mask) {
    GEMM_SHARED;
    int h = blockIdx.z;
    int row0 = blockIdx.y * 128, n0 = blockIdx.x * 64;
    gemm_core(g_qh + ((size_t)h * NTOK + row0) * HD, g_ql + ((size_t)h * NTOK + row0) * HD, HD,
              g_kh + ((size_t)h * NTOK + n0) * HD,  g_kl + ((size_t)h * NTOK + n0) * HD,  HD,
              64, HD, 2, sbase, acc);
    float* bb = g_bias + ((size_t)h << 20);
    #pragma unroll
    for (int f = 0; f < 2; f++)
        #pragma unroll
        for (int nf = 0; nf < 4; nf++)
            #pragma unroll
            for (int i = 0; i < 4; i++) {
                int row = row0 + erow + f * 16 + (i >> 1) * 8;
                int col = n0 + ecol + nf * 8 + (i & 1);
                float mr = __ldg(mask + row), mc = __ldg(mask + col);
                bb[(size_t)row * NTOK + col] += acc[f][nf][i] + 1e9f * (mr * mc - 1.f);
            }
}

// ---- softmax -> normalized bf16 splits ----
__global__ void k_softmax(int dummy) {
    int row = blockIdx.x, h = blockIdx.y, tid = threadIdx.x;
    const float* p = g_bias + ((size_t)h << 20) + (size_t)row * NTOK + tid * 4;
    float4 v = *(const float4*)p;
    __shared__ float red[8], red2[8];
    float m = fmaxf(fmaxf(v.x, v.y), fmaxf(v.z, v.w));
    #pragma unroll
    for (int o = 16; o; o >>= 1) m = fmaxf(m, __shfl_xor_sync(0xffffffffu, m, o));
    if ((tid & 31) == 0) red[tid >> 5] = m;
    __syncthreads();
    m = red[tid & 7];
    #pragma unroll
    for (int o = 4; o; o >>= 1) m = fmaxf(m, __shfl_xor_sync(0xffffffffu, m, o));

    v.x = __expf(v.x - m); v.y = __expf(v.y - m);
    v.z = __expf(v.z - m); v.w = __expf(v.w - m);
    float s = v.x + v.y + v.z + v.w;
    #pragma unroll
    for (int o = 16; o; o >>= 1) s += __shfl_xor_sync(0xffffffffu, s, o);
    if ((tid & 31) == 0) red2[tid >> 5] = s;
    __syncthreads();
    s = red2[tid & 7];
    #pragma unroll
    for (int o = 4; o; o >>= 1) s += __shfl_xor_sync(0xffffffffu, s, o);
    float inv = 1.f / s;
    size_t base = ((size_t)h << 20) + (size_t)row * NTOK + tid * 4;
    float pv[4] = {v.x * inv, v.y * inv, v.z * inv, v.w * inv};
    #pragma unroll
    for (int j = 0; j < 4; j++) {
        bf16 hh = __float2bfloat16(pv[j]);
        g_ph[base + j] = hh;
        g_pl[base + j] = __float2bfloat16(pv[j] - __bfloat162float(hh));
    }
}

// ---- PV ----
__global__ __launch_bounds__(256)
void k_gemm_pv(int dummy) {
    GEMM_SHARED;
    int h = blockIdx.z;
    int row0 = blockIdx.y * 128;
    gemm_core(g_ph + ((size_t)h << 20) + (size_t)row0 * NTOK,
              g_pl + ((size_t)h << 20) + (size_t)row0 * NTOK, NTOK,
              g_vth + (size_t)h * HD * NTOK, g_vtl + (size_t)h * HD * NTOK, NTOK,
              HD, NTOK, NTOK / 32, sbase, acc);
    #pragma unroll
    for (int f = 0; f < 2; f++)
        #pragma unroll
        for (int nf = 0; nf < 4; nf++)
            #pragma unroll
            for (int i = 0; i < 4; i++) {
                int row = row0 + erow + f * 16 + (i >> 1) * 8;
                int col = ecol + nf * 8 + (i & 1);
                if (col < HD) {
                    size_t idx = (size_t)row * HDQ + h * HD + col;
                    float o = acc[f][nf][i] * g_gate[idx];
                    bf16 hh = __float2bfloat16(o);
                    g_ogh[idx] = hh;
                    g_ogl[idx] = __float2bfloat16(o - __bfloat162float(hh));
                }
            }
}

// ---- out projection ----
__global__ __launch_bounds__(256)
void k_gemm_out(const float* __restrict__ bo, float* __restrict__ out) {
    GEMM_SHARED;
    int row0 = blockIdx.y * 128, n0 = blockIdx.x * 64;
    const bf16* Bh = g_wTh + 4ull * CQ * CQ + (size_t)n0 * CQ;
    const bf16* Bl = g_wTl + 4ull * CQ * CQ + (size_t)n0 * CQ;
    gemm_core(g_ogh + (size_t)row0 * CQ, g_ogl + (size_t)row0 * CQ, CQ,
              Bh, Bl, CQ, 64, CQ, CQ / 32, sbase, acc);
    #pragma unroll
    for (int f = 0; f < 2; f++)
        #pragma unroll
        for (int nf = 0; nf < 4; nf++)
            #pragma unroll
            for (int i = 0; i < 4; i++) {
                int row = row0 + erow + f * 16 + (i >> 1) * 8;
                int col = n0 + ecol + nf * 8 + (i & 1);
                out[(size_t)row * CQ + col] = acc[f][nf][i] + __ldg(bo + col);
            }
}

// ================= launch =================
extern "C" void kernel_launch(void* const* d_in, const int* in_sizes, int n_in,
                              void* d_out, int out_size) {
    const float* a    = (const float*)d_in[0];
    const float* z    = (const float*)d_in[1];
    const float* mask = (const float*)d_in[2];
    const float* ga   = (const float*)d_in[3];
    const float* ba   = (const float*)d_in[4];
    const float* gz   = (const float*)d_in[5];
    const float* bz   = (const float*)d_in[6];
    const float* wz   = (const float*)d_in[7];
    const float* wq   = (const float*)d_in[8];
    const float* wk   = (const float*)d_in[9];
    const float* wv   = (const float*)d_in[10];
    const float* wg   = (const float*)d_in[11];
    const float* bg   = (const float*)d_in[12];
    const float* wo   = (const float*)d_in[13];
    const float* bo   = (const float*)d_in[14];
    float* out = (float*)d_out;

    cudaFuncSetAttribute(k_pair_bias,   cudaFuncAttributeMaxDynamicSharedMemorySize, PB_SMEM_FLOATS * 4);
    cudaFuncSetAttribute(k_gemm_qkvg,   cudaFuncAttributeMaxDynamicSharedMemorySize, GEMM_SMEM);
    cudaFuncSetAttribute(k_gemm_scores, cudaFuncAttributeMaxDynamicSharedMemorySize, GEMM_SMEM);
    cudaFuncSetAttribute(k_gemm_pv,     cudaFuncAttributeMaxDynamicSharedMemorySize, GEMM_SMEM);
    cudaFuncSetAttribute(k_gemm_out,    cudaFuncAttributeMaxDynamicSharedMemorySize, GEMM_SMEM);

    k_pair_bias<<<4096, 256, PB_SMEM_FLOATS * 4>>>(z, gz, bz, wz);
    k_ln_a<<<1024, 256>>>(a, ga, ba);
    k_splitw<<<dim3(CQ * CQ / 256, 5), 256>>>(wq, wk, wv, wg, wo);

    k_gemm_qkvg<<<dim3(12, 8, 4), 256, GEMM_SMEM>>>(bg);
    k_gemm_scores<<<dim3(16, 8, NH), 256, GEMM_SMEM>>>(mask);
    k_softmax<<<dim3(NTOK, NH), 256>>>(0);
    k_gemm_pv<<<dim3(1, 8, NH), 256, GEMM_SMEM>>>(0);
    k_gemm_out<<<dim3(12, 8), 256, GEMM_SMEM>>>(bo, out);
}

// round 14
// speedup vs baseline: 1.0129x; 1.0129x over previous
#include <cuda_runtime.h>
#include <cuda_bf16.h>
#include <cstdint>

typedef unsigned long long ULL;
typedef __nv_bfloat16 bf16;

#define NTOK 1024
#define CQ   768
#define CZ   128
#define NH   16
#define HD   48
#define HDQ  768
#define QSCALE 0.14433756729740643f  // 1/sqrt(48)

// ================= f32x2 helpers (pair_bias) =================
__device__ __forceinline__ ULL fma2(ULL a, ULL b, ULL c) {
    ULL d; asm("fma.rn.f32x2 %0, %1, %2, %3;" : "=l"(d) : "l"(a), "l"(b), "l"(c)); return d;
}
__device__ __forceinline__ ULL add2(ULL a, ULL b) {
    ULL d; asm("add.rn.f32x2 %0, %1, %2;" : "=l"(d) : "l"(a), "l"(b)); return d;
}
__device__ __forceinline__ float lo2(ULL u){ return __uint_as_float((unsigned)u); }
__device__ __forceinline__ float hi2(ULL u){ return __uint_as_float((unsigned)(u >> 32)); }

// ================= mma.sync helpers =================
__device__ __forceinline__ uint32_t s2u(const void* p){
    uint32_t a; asm("{ .reg .u64 t; cvta.to.shared.u64 t, %1; cvt.u32.u64 %0, t; }" : "=r"(a) : "l"(p));
    return a;
}
__device__ __forceinline__ void ldsm4(uint32_t* r, uint32_t addr){
    asm volatile("ldmatrix.sync.aligned.m8n8.x4.shared.b16 {%0,%1,%2,%3}, [%4];"
        : "=r"(r[0]), "=r"(r[1]), "=r"(r[2]), "=r"(r[3]) : "r"(addr));
}
__device__ __forceinline__ void mma16816(float* c, uint32_t a0, uint32_t a1, uint32_t a2, uint32_t a3,
                                         uint32_t b0, uint32_t b1){
    asm volatile("mma.sync.aligned.m16n8k16.row.col.f32.bf16.bf16.f32 "
        "{%0,%1,%2,%3}, {%4,%5,%6,%7}, {%8,%9}, {%0,%1,%2,%3};"
        : "+f"(c[0]), "+f"(c[1]), "+f"(c[2]), "+f"(c[3])
        : "r"(a0), "r"(a1), "r"(a2), "r"(a3), "r"(b0), "r"(b1));
}
__device__ __forceinline__ void cpa16(uint32_t dst, const void* src, bool p){
    int sz = p ? 16 : 0;
    asm volatile("cp.async.cg.shared.global [%0], [%1], 16, %2;"
        :: "r"(dst), "l"(src), "r"(sz) : "memory");
}
#define CP_COMMIT() asm volatile("cp.async.commit_group;" ::: "memory")
#define CP_WAIT(N)  asm volatile("cp.async.wait_group %0;" :: "n"(N) : "memory")

// ================= scratch =================
__device__ float g_bias[(size_t)NH * NTOK * NTOK];
__device__ bf16  g_anh[NTOK * CQ], g_anl[NTOK * CQ];
__device__ bf16  g_wTh[5u * CQ * CQ], g_wTl[5u * CQ * CQ];   // [n][k]
__device__ bf16  g_qh[NH * NTOK * HD], g_ql[NH * NTOK * HD];
__device__ bf16  g_kh[NH * NTOK * HD], g_kl[NH * NTOK * HD];
__device__ bf16  g_vth[NH * HD * NTOK], g_vtl[NH * HD * NTOK]; // [h][d][tok]
__device__ bf16  g_ph[(size_t)NH * NTOK * NTOK], g_pl[(size_t)NH * NTOK * NTOK];
__device__ float g_gate[NTOK * HDQ];
__device__ bf16  g_ogh[NTOK * HDQ], g_ogl[NTOK * HDQ];

// ================= LayerNorm of a -> bf16 splits =================
__global__ void k_ln_a(const float* __restrict__ a, const float* __restrict__ g,
                       const float* __restrict__ b) {
    int row = blockIdx.x, tid = threadIdx.x;
    const float* x = a + (size_t)row * CQ;
    float v0 = x[tid], v1 = x[tid + 256], v2 = x[tid + 512];
    float s = v0 + v1 + v2;
    float ss = v0*v0 + v1*v1 + v2*v2;
    __shared__ float sred[8], sred2[8];
    #pragma unroll
    for (int o = 16; o; o >>= 1) {
        s  += __shfl_xor_sync(0xffffffffu, s, o);
        ss += __shfl_xor_sync(0xffffffffu, ss, o);
    }
    if ((tid & 31) == 0) { sred[tid >> 5] = s; sred2[tid >> 5] = ss; }
    __syncthreads();
    if (tid == 0) {
        float S = 0, SS = 0;
        for (int i = 0; i < 8; i++) { S += sred[i]; SS += sred2[i]; }
        float mu = S * (1.0f / CQ);
        float var = SS * (1.0f / CQ) - mu * mu;
        sred[0] = mu; sred2[0] = rsqrtf(var + 1e-5f);
    }
    __syncthreads();
    float mu = sred[0], rstd = sred2[0];
    #pragma unroll
    for (int j = 0; j < 3; j++) {
        int c = tid + j * 256;
        float v = (j == 0 ? v0 : j == 1 ? v1 : v2);
        float vn = (v - mu) * rstd * g[c] + b[c];
        bf16 h = __float2bfloat16(vn);
        g_anh[(size_t)row * CQ + c] = h;
        g_anl[(size_t)row * CQ + c] = __float2bfloat16(vn - __bfloat162float(h));
    }
}

// ================= weight transpose + split =================
__global__ void k_splitw(const float* w0, const float* w1, const float* w2,
                         const float* w3, const float* w4) {
    int which = blockIdx.y;
    const float* w = (which == 0) ? w0 : (which == 1) ? w1 : (which == 2) ? w2 :
                     (which == 3) ? w3 : w4;
    int idx = blockIdx.x * 256 + threadIdx.x;   // k*768 + n
    int k = idx / CQ, n = idx - k * CQ;
    float v = w[idx];
    bf16 h = __float2bfloat16(v);
    size_t off = (size_t)which * CQ * CQ + (size_t)n * CQ + k;
    g_wTh[off] = h;
    g_wTl[off] = __float2bfloat16(v - __bfloat162float(h));
}

// ================= pair bias (SIMT, DRAM-bound) =================
#define PB_SMEM_FLOATS (2*256*32 + 2048 + 32)
__global__ __launch_bounds__(256, 2)
void k_pair_bias(const float* __restrict__ z, const float* __restrict__ gz,
                 const float* __restrict__ bz, const float* __restrict__ wz) {
    extern __shared__ float sm[];
    float* zb    = sm;
    float* wps   = sm + 16384;
    float* cs_cb = wps + 2048;

    int tid = threadIdx.x;
    for (int i = tid; i < CZ * NH; i += 256) {
        int c = i >> 4, h = i & 15;
        wps[(c >> 1) * 32 + h * 2 + (c & 1)] = gz[c] * wz[c * NH + h];
    }
    __syncthreads();
    if (tid < 16) {
        float cs = 0.f, cb = 0.f;
        for (int c = 0; c < CZ; c++) {
            cs += wps[(c >> 1) * 32 + tid * 2 + (c & 1)];
            cb += bz[c] * wz[c * NH + tid];
        }
        cs_cb[tid] = cs; cs_cb[16 + tid] = cb;
    }
    __syncthreads();

    int tile = blockIdx.x;
    const float4* zg = (const float4*)(z + (size_t)tile * 256 * CZ);

    int srow[8], sf[8];
    #pragma unroll
    for (int j = 0; j < 8; j++) { int i = tid + j * 256; srow[j] = i >> 3; sf[j] = i & 7; }

    float4 pre[8];
    #pragma unroll
    for (int j = 0; j < 8; j++)
        pre[j] = zg[(size_t)srow[j] * 32 + sf[j]];

    ULL acc[NH];
    #pragma unroll
    for (int h = 0; h < NH; h++) acc[h] = 0ULL;
    ULL sum2 = 0ULL, ss2 = 0ULL;

    for (int c = 0; c < 4; c++) {
        float* buf = zb + (c & 1) * 8192;
        #pragma unroll
        for (int j = 0; j < 8; j++)
            *(float4*)(buf + srow[j] * 32 + ((sf[j] + srow[j]) & 7) * 4) = pre[j];
        __syncthreads();
        if (c < 3) {
            #pragma unroll
            for (int j = 0; j < 8; j++)
                pre[j] = zg[(size_t)srow[j] * 32 + (c + 1) * 8 + sf[j]];
        }
        #pragma unroll
        for (int j = 0; j < 8; j++) {
            int pos = (j + tid) & 7;
            float4 zv = *(const float4*)(buf + tid * 32 + pos * 4);
            ULL z01 = ((const ULL*)&zv)[0];
            ULL z23 = ((const ULL*)&zv)[1];
            sum2 = add2(sum2, add2(z01, z23));
            ss2  = fma2(z01, z01, fma2(z23, z23, ss2));
            int p0 = c * 16 + 2 * j;
            const float4* w0 = (const float4*)(wps + p0 * 32);
            const float4* w1 = (const float4*)(wps + p0 * 32 + 32);
            #pragma unroll
            for (int h2 = 0; h2 < 8; h2++) {
                float4 wa = w0[h2];
                float4 wb = w1[h2];
                acc[2*h2]     = fma2(z01, ((const ULL*)&wa)[0], acc[2*h2]);
                acc[2*h2 + 1] = fma2(z01, ((const ULL*)&wa)[1], acc[2*h2 + 1]);
                acc[2*h2]     = fma2(z23, ((const ULL*)&wb)[0], acc[2*h2]);
                acc[2*h2 + 1] = fma2(z23, ((const ULL*)&wb)[1], acc[2*h2 + 1]);
            }
        }
        __syncthreads();
    }

    float sum = lo2(sum2) + hi2(sum2);
    float ss  = lo2(ss2)  + hi2(ss2);
    float mu  = sum * (1.0f / CZ);
    float var = ss * (1.0f / CZ) - mu * mu;
    float rstd = rsqrtf(var + 1e-5f);

    float* outs = zb;
    #pragma unroll
    for (int h = 0; h < NH; h++) {
        float d = lo2(acc[h]) + hi2(acc[h]);
        outs[h * 256 + tid] = rstd * (d - mu * cs_cb[h]) + cs_cb[16 + h];
    }
    __syncthreads();
    #pragma unroll
    for (int it = 0; it < 4; it++) {
        int idx = tid + it * 256;
        int h = idx >> 6, j4 = idx & 63;
        float4 v = *(const float4*)(outs + h * 256 + j4 * 4);
        *(float4*)(g_bias + ((size_t)h << 20) + (size_t)tile * 256 + j4 * 4) = v;
    }
}

// ================= bf16x3 mma.sync GEMM core, 2-stage cp.async pipeline =================
#define ASTR 40
#define ST_AL 10240u
#define ST_BH 20480u
#define ST_BL 25600u
#define STAGE_BYTES 30720u
#define GEMM_SMEM (2 * STAGE_BYTES)

__device__ __forceinline__ void stage_chunk(
    const bf16* __restrict__ Ah, const bf16* __restrict__ Al, int lda,
    const bf16* __restrict__ Bh, const bf16* __restrict__ Bl, int ldb, int nrealB,
    int k0, int Kreal, uint32_t sb)
{
    int tid = threadIdx.x;
    #pragma unroll
    for (int j = 0; j < 2; j++) {
        int i = tid + j * 256;                 // < 512
        int r = i >> 2, g = i & 3, k = k0 + g * 8;
        bool p = (k < Kreal);
        const bf16* sa = p ? (Ah + (size_t)r * lda + k) : Ah;
        const bf16* sl = p ? (Al + (size_t)r * lda + k) : Al;
        uint32_t doff = (uint32_t)(r * ASTR + g * 8) * 2;
        cpa16(sb + doff, sa, p);
        cpa16(sb + ST_AL + doff, sl, p);
    }
    {
        int r = tid >> 2, g = tid & 3, k = k0 + g * 8;
        bool p = (r < nrealB) && (k < Kreal);
        const bf16* sbh = p ? (Bh + (size_t)r * ldb + k) : Bh;
        const bf16* sbl = p ? (Bl + (size_t)r * ldb + k) : Bl;
        uint32_t doff = (uint32_t)(r * ASTR + g * 8) * 2;
        cpa16(sb + ST_BH + doff, sbh, p);
        cpa16(sb + ST_BL + doff, sbl, p);
    }
    CP_COMMIT();
}

__device__ __forceinline__ void gemm_core(
    const bf16* __restrict__ Ah, const bf16* __restrict__ Al, int lda,
    const bf16* __restrict__ Bh, const bf16* __restrict__ Bl, int ldb, int nrealB,
    int Kreal, int nchunks, uint32_t sbase, float acc[2][4][4])
{
    int lane = threadIdx.x & 31, wid = threadIdx.x >> 5;
    int wm = wid & 3, wn = wid >> 2;
    #pragma unroll
    for (int f = 0; f < 2; f++)
        #pragma unroll
        for (int nf = 0; nf < 4; nf++)
            #pragma unroll
            for (int i = 0; i < 4; i++) acc[f][nf][i] = 0.f;

    int sub = lane >> 3, rin = lane & 7;
    int rowoff = ((sub & 1) << 3) + rin;
    int koff = (sub >> 1) << 3;

    stage_chunk(Ah, Al, lda, Bh, Bl, ldb, nrealB, 0, Kreal, sbase);

    for (int c = 0; c < nchunks; c++) {
        uint32_t sb = sbase + (uint32_t)(c & 1) * STAGE_BYTES;
        if (c + 1 < nchunks) {
            stage_chunk(Ah, Al, lda, Bh, Bl, ldb, nrealB, (c + 1) * 32, Kreal,
                        sbase + (uint32_t)((c + 1) & 1) * STAGE_BYTES);
            CP_WAIT(1);
        } else {
            CP_WAIT(0);
        }
        __syncthreads();

        #pragma unroll
        for (int s = 0; s < 2; s++) {
            uint32_t ah[2][4], al[2][4], bh[2][4], bl[2][4];
            #pragma unroll
            for (int f = 0; f < 2; f++) {
                uint32_t off = (uint32_t)((wm * 32 + f * 16 + rowoff) * ASTR + s * 16 + koff) * 2;
                ldsm4(ah[f], sb + off);
                ldsm4(al[f], sb + ST_AL + off);
            }
            #pragma unroll
            for (int g2 = 0; g2 < 2; g2++) {
                uint32_t off = (uint32_t)((wn * 32 + g2 * 16 + rowoff) * ASTR + s * 16 + koff) * 2;
                ldsm4(bh[g2], sb + ST_BH + off);
                ldsm4(bl[g2], sb + ST_BL + off);
            }
            #pragma unroll
            for (int f = 0; f < 2; f++)
                #pragma unroll
                for (int nf = 0; nf < 4; nf++) {
                    int g2 = nf >> 1, o = nf & 1;
                    mma16816(acc[f][nf], ah[f][0], ah[f][1], ah[f][2], ah[f][3],
                             bh[g2][o], bh[g2][2 + o]);
                    mma16816(acc[f][nf], ah[f][0], ah[f][1], ah[f][2], ah[f][3],
                             bl[g2][o], bl[g2][2 + o]);
                    mma16816(acc[f][nf], al[f][0], al[f][1], al[f][2], al[f][3],
                             bh[g2][o], bh[g2][2 + o]);
                }
        }
        __syncthreads();
    }
}

#define GEMM_SHARED \
    extern __shared__ char dsm[]; \
    uint32_t sbase = s2u(dsm); \
    float acc[2][4][4]; \
    int lane = threadIdx.x & 31, wid = threadIdx.x >> 5; \
    int wm = wid & 3, wn = wid >> 2; \
    int erow = wm * 32 + (lane >> 2); \
    int ecol = wn * 32 + (lane & 3) * 2;

// ---- QKVG ----
__global__ __launch_bounds__(256)
void k_gemm_qkvg(const float* __restrict__ bg) {
    GEMM_SHARED;
    int mode = blockIdx.z;
    int row0 = blockIdx.y * 128, n0 = blockIdx.x * 64;
    const bf16* Bh = g_wTh + (size_t)mode * CQ * CQ + (size_t)n0 * CQ;
    const bf16* Bl = g_wTl + (size_t)mode * CQ * CQ + (size_t)n0 * CQ;
    gemm_core(g_anh + (size_t)row0 * CQ, g_anl + (size_t)row0 * CQ, CQ,
              Bh, Bl, CQ, 64, CQ, CQ / 32, sbase, acc);
    #pragma unroll
    for (int f = 0; f < 2; f++)
        #pragma unroll
        for (int nf = 0; nf < 4; nf++)
            #pragma unroll
            for (int i = 0; i < 4; i++) {
                int row = row0 + erow + f * 16 + (i >> 1) * 8;
                int col = n0 + ecol + nf * 8 + (i & 1);
                float v = acc[f][nf][i];
                int h = col / HD, d = col - h * HD;
                if (mode == 0) {
                    float q = v * QSCALE;
                    bf16 hh = __float2bfloat16(q);
                    g_qh[((size_t)h * NTOK + row) * HD + d] = hh;
                    g_ql[((size_t)h * NTOK + row) * HD + d] = __float2bfloat16(q - __bfloat162float(hh));
                } else if (mode == 1) {
                    bf16 hh = __float2bfloat16(v);
                    g_kh[((size_t)h * NTOK + row) * HD + d] = hh;
                    g_kl[((size_t)h * NTOK + row) * HD + d] = __float2bfloat16(v - __bfloat162float(hh));
                } else if (mode == 2) {
                    bf16 hh = __float2bfloat16(v);
                    g_vth[((size_t)h * HD + d) * NTOK + row] = hh;
                    g_vtl[((size_t)h * HD + d) * NTOK + row] = __float2bfloat16(v - __bfloat162float(hh));
                } else {
                    g_gate[(size_t)row * HDQ + col] = 1.f / (1.f + __expf(-(v + bg[col])));
                }
            }
}

// ---- scores ----
__global__ __launch_bounds__(256)
void k_gemm_scores(const float* __restrict__ mask) {
    GEMM_SHARED;
    int h = blockIdx.z;
    int row0 = blockIdx.y * 128, n0 = blockIdx.x * 64;
    gemm_core(g_qh + ((size_t)h * NTOK + row0) * HD, g_ql + ((size_t)h * NTOK + row0) * HD, HD,
              g_kh + ((size_t)h * NTOK + n0) * HD,  g_kl + ((size_t)h * NTOK + n0) * HD,  HD,
              64, HD, 2, sbase, acc);
    float* bb = g_bias + ((size_t)h << 20);
    #pragma unroll
    for (int f = 0; f < 2; f++)
        #pragma unroll
        for (int nf = 0; nf < 4; nf++)
            #pragma unroll
            for (int i = 0; i < 4; i++) {
                int row = row0 + erow + f * 16 + (i >> 1) * 8;
                int col = n0 + ecol + nf * 8 + (i & 1);
                float mr = __ldg(mask + row), mc = __ldg(mask + col);
                bb[(size_t)row * NTOK + col] += acc[f][nf][i] + 1e9f * (mr * mc - 1.f);
            }
}

// ---- softmax -> normalized bf16 splits ----
__global__ void k_softmax(int dummy) {
    int row = blockIdx.x, h = blockIdx.y, tid = threadIdx.x;
    const float* p = g_bias + ((size_t)h << 20) + (size_t)row * NTOK + tid * 4;
    float4 v = *(const float4*)p;
    __shared__ float red[8], red2[8];
    float m = fmaxf(fmaxf(v.x, v.y), fmaxf(v.z, v.w));
    #pragma unroll
    for (int o = 16; o; o >>= 1) m = fmaxf(m, __shfl_xor_sync(0xffffffffu, m, o));
    if ((tid & 31) == 0) red[tid >> 5] = m;
    __syncthreads();
    m = red[tid & 7];
    #pragma unroll
    for (int o = 4; o; o >>= 1) m = fmaxf(m, __shfl_xor_sync(0xffffffffu, m, o));

    v.x = __expf(v.x - m); v.y = __expf(v.y - m);
    v.z = __expf(v.z - m); v.w = __expf(v.w - m);
    float s = v.x + v.y + v.z + v.w;
    #pragma unroll
    for (int o = 16; o; o >>= 1) s += __shfl_xor_sync(0xffffffffu, s, o);
    if ((tid & 31) == 0) red2[tid >> 5] = s;
    __syncthreads();
    s = red2[tid & 7];
    #pragma unroll
    for (int o = 4; o; o >>= 1) s += __shfl_xor_sync(0xffffffffu, s, o);
    float inv = 1.f / s;
    size_t base = ((size_t)h << 20) + (size_t)row * NTOK + tid * 4;
    float pv[4] = {v.x * inv, v.y * inv, v.z * inv, v.w * inv};
    #pragma unroll
    for (int j = 0; j < 4; j++) {
        bf16 hh = __float2bfloat16(pv[j]);
        g_ph[base + j] = hh;
        g_pl[base + j] = __float2bfloat16(pv[j] - __bfloat162float(hh));
    }
}

// ---- PV ----
__global__ __launch_bounds__(256)
void k_gemm_pv(int dummy) {
    GEMM_SHARED;
    int h = blockIdx.z;
    int row0 = blockIdx.y * 128;
    gemm_core(g_ph + ((size_t)h << 20) + (size_t)row0 * NTOK,
              g_pl + ((size_t)h << 20) + (size_t)row0 * NTOK, NTOK,
              g_vth + (size_t)h * HD * NTOK, g_vtl + (size_t)h * HD * NTOK, NTOK,
              HD, NTOK, NTOK / 32, sbase, acc);
    #pragma unroll
    for (int f = 0; f < 2; f++)
        #pragma unroll
        for (int nf = 0; nf < 4; nf++)
            #pragma unroll
            for (int i = 0; i < 4; i++) {
                int row = row0 + erow + f * 16 + (i >> 1) * 8;
                int col = ecol + nf * 8 + (i & 1);
                if (col < HD) {
                    size_t idx = (size_t)row * HDQ + h * HD + col;
                    float o = acc[f][nf][i] * g_gate[idx];
                    bf16 hh = __float2bfloat16(o);
                    g_ogh[idx] = hh;
                    g_ogl[idx] = __float2bfloat16(o - __bfloat162float(hh));
                }
            }
}

// ---- out projection ----
__global__ __launch_bounds__(256)
void k_gemm_out(const float* __restrict__ bo, float* __restrict__ out) {
    GEMM_SHARED;
    int row0 = blockIdx.y * 128, n0 = blockIdx.x * 64;
    const bf16* Bh = g_wTh + 4ull * CQ * CQ + (size_t)n0 * CQ;
    const bf16* Bl = g_wTl + 4ull * CQ * CQ + (size_t)n0 * CQ;
    gemm_core(g_ogh + (size_t)row0 * CQ, g_ogl + (size_t)row0 * CQ, CQ,
              Bh, Bl, CQ, 64, CQ, CQ / 32, sbase, acc);
    #pragma unroll
    for (int f = 0; f < 2; f++)
        #pragma unroll
        for (int nf = 0; nf < 4; nf++)
            #pragma unroll
            for (int i = 0; i < 4; i++) {
                int row = row0 + erow + f * 16 + (i >> 1) * 8;
                int col = n0 + ecol + nf * 8 + (i & 1);
                out[(size_t)row * CQ + col] = acc[f][nf][i] + __ldg(bo + col);
            }
}

// ================= launch =================
extern "C" void kernel_launch(void* const* d_in, const int* in_sizes, int n_in,
                              void* d_out, int out_size) {
    const float* a    = (const float*)d_in[0];
    const float* z    = (const float*)d_in[1];
    const float* mask = (const float*)d_in[2];
    const float* ga   = (const float*)d_in[3];
    const float* ba   = (const float*)d_in[4];
    const float* gz   = (const float*)d_in[5];
    const float* bz   = (const float*)d_in[6];
    const float* wz   = (const float*)d_in[7];
    const float* wq   = (const float*)d_in[8];
    const float* wk   = (const float*)d_in[9];
    const float* wv   = (const float*)d_in[10];
    const float* wg   = (const float*)d_in[11];
    const float* bg   = (const float*)d_in[12];
    const float* wo   = (const float*)d_in[13];
    const float* bo   = (const float*)d_in[14];
    float* out = (float*)d_out;

    cudaFuncSetAttribute(k_pair_bias,   cudaFuncAttributeMaxDynamicSharedMemorySize, PB_SMEM_FLOATS * 4);
    cudaFuncSetAttribute(k_gemm_qkvg,   cudaFuncAttributeMaxDynamicSharedMemorySize, GEMM_SMEM);
    cudaFuncSetAttribute(k_gemm_scores, cudaFuncAttributeMaxDynamicSharedMemorySize, GEMM_SMEM);
    cudaFuncSetAttribute(k_gemm_pv,     cudaFuncAttributeMaxDynamicSharedMemorySize, GEMM_SMEM);
    cudaFuncSetAttribute(k_gemm_out,    cudaFuncAttributeMaxDynamicSharedMemorySize, GEMM_SMEM);

    // ---- two-arm overlap: pair_bias (DRAM-bound) || ln+splitw+qkvg (tensor-bound) ----
    cudaStream_t s1;
    cudaEvent_t e_fork, e_join;
    cudaStreamCreateWithFlags(&s1, cudaStreamNonBlocking);
    cudaEventCreateWithFlags(&e_fork, cudaEventDisableTiming);
    cudaEventCreateWithFlags(&e_join, cudaEventDisableTiming);

    cudaEventRecord(e_fork, 0);
    cudaStreamWaitEvent(s1, e_fork, 0);

    // Arm A (s1): pair bias over 537 MB of z
    k_pair_bias<<<4096, 256, PB_SMEM_FLOATS * 4, s1>>>(z, gz, bz, wz);
    cudaEventRecord(e_join, s1);

    // Arm B (default stream): LN -> weight split -> QKVG projections
    k_ln_a<<<1024, 256>>>(a, ga, ba);
    k_splitw<<<dim3(CQ * CQ / 256, 5), 256>>>(wq, wk, wv, wg, wo);
    k_gemm_qkvg<<<dim3(12, 8, 4), 256, GEMM_SMEM>>>(bg);

    // join: scores needs g_bias (Arm A) + q/k (Arm B)
    cudaStreamWaitEvent(0, e_join, 0);

    k_gemm_scores<<<dim3(16, 8, NH), 256, GEMM_SMEM>>>(mask);
    k_softmax<<<dim3(NTOK, NH), 256>>>(0);
    k_gemm_pv<<<dim3(1, 8, NH), 256, GEMM_SMEM>>>(0);
    k_gemm_out<<<dim3(12, 8), 256, GEMM_SMEM>>>(bo, out);
}

// round 16
// speedup vs baseline: 1.2147x; 1.1992x over previous
#include <cuda_runtime.h>
#include <cuda_bf16.h>
#include <cstdint>

typedef unsigned long long ULL;
typedef __nv_bfloat16 bf16;

#define NTOK 1024
#define CQ   768
#define CZ   128
#define NH   16
#define HD   48
#define HDQ  768
#define QSCALE 0.14433756729740643f  // 1/sqrt(48)

// ================= f32x2 helpers (pair_bias) =================
__device__ __forceinline__ ULL fma2(ULL a, ULL b, ULL c) {
    ULL d; asm("fma.rn.f32x2 %0, %1, %2, %3;" : "=l"(d) : "l"(a), "l"(b), "l"(c)); return d;
}
__device__ __forceinline__ ULL add2(ULL a, ULL b) {
    ULL d; asm("add.rn.f32x2 %0, %1, %2;" : "=l"(d) : "l"(a), "l"(b)); return d;
}
__device__ __forceinline__ float lo2(ULL u){ return __uint_as_float((unsigned)u); }
__device__ __forceinline__ float hi2(ULL u){ return __uint_as_float((unsigned)(u >> 32)); }

// ================= mma.sync helpers =================
__device__ __forceinline__ uint32_t s2u(const void* p){
    uint32_t a; asm("{ .reg .u64 t; cvta.to.shared.u64 t, %1; cvt.u32.u64 %0, t; }" : "=r"(a) : "l"(p));
    return a;
}
__device__ __forceinline__ void ldsm4(uint32_t* r, uint32_t addr){
    asm volatile("ldmatrix.sync.aligned.m8n8.x4.shared.b16 {%0,%1,%2,%3}, [%4];"
        : "=r"(r[0]), "=r"(r[1]), "=r"(r[2]), "=r"(r[3]) : "r"(addr));
}
__device__ __forceinline__ void mma16816(float* c, uint32_t a0, uint32_t a1, uint32_t a2, uint32_t a3,
                                         uint32_t b0, uint32_t b1){
    asm volatile("mma.sync.aligned.m16n8k16.row.col.f32.bf16.bf16.f32 "
        "{%0,%1,%2,%3}, {%4,%5,%6,%7}, {%8,%9}, {%0,%1,%2,%3};"
        : "+f"(c[0]), "+f"(c[1]), "+f"(c[2]), "+f"(c[3])
        : "r"(a0), "r"(a1), "r"(a2), "r"(a3), "r"(b0), "r"(b1));
}
__device__ __forceinline__ void cpa16(uint32_t dst, const void* src, bool p){
    int sz = p ? 16 : 0;
    asm volatile("cp.async.cg.shared.global [%0], [%1], 16, %2;"
        :: "r"(dst), "l"(src), "r"(sz) : "memory");
}
#define CP_COMMIT() asm volatile("cp.async.commit_group;" ::: "memory")
#define CP_WAIT(N)  asm volatile("cp.async.wait_group %0;" :: "n"(N) : "memory")

__device__ __forceinline__ uint32_t pkb(bf16 lo, bf16 hi){
    return ((uint32_t)__bfloat16_as_ushort(hi) << 16) | (uint32_t)__bfloat16_as_ushort(lo);
}

// ================= scratch =================
__device__ float g_bias[(size_t)NH * NTOK * NTOK];
__device__ bf16  g_anh[NTOK * CQ], g_anl[NTOK * CQ];
__device__ bf16  g_wTh[5u * CQ * CQ], g_wTl[5u * CQ * CQ];   // [n][k]
__device__ bf16  g_qh[NH * NTOK * HD], g_ql[NH * NTOK * HD];
__device__ bf16  g_kh[NH * NTOK * HD], g_kl[NH * NTOK * HD];
__device__ bf16  g_vth[NH * HD * NTOK], g_vtl[NH * HD * NTOK]; // [h][d][tok]
__device__ float g_gate[NTOK * HDQ];
__device__ bf16  g_ogh[NTOK * HDQ], g_ogl[NTOK * HDQ];

// ================= LayerNorm of a -> bf16 splits =================
__global__ void k_ln_a(const float* __restrict__ a, const float* __restrict__ g,
                       const float* __restrict__ b) {
    int row = blockIdx.x, tid = threadIdx.x;
    const float* x = a + (size_t)row * CQ;
    float v0 = x[tid], v1 = x[tid + 256], v2 = x[tid + 512];
    float s = v0 + v1 + v2;
    float ss = v0*v0 + v1*v1 + v2*v2;
    __shared__ float sred[8], sred2[8];
    #pragma unroll
    for (int o = 16; o; o >>= 1) {
        s  += __shfl_xor_sync(0xffffffffu, s, o);
        ss += __shfl_xor_sync(0xffffffffu, ss, o);
    }
    if ((tid & 31) == 0) { sred[tid >> 5] = s; sred2[tid >> 5] = ss; }
    __syncthreads();
    if (tid == 0) {
        float S = 0, SS = 0;
        for (int i = 0; i < 8; i++) { S += sred[i]; SS += sred2[i]; }
        float mu = S * (1.0f / CQ);
        float var = SS * (1.0f / CQ) - mu * mu;
        sred[0] = mu; sred2[0] = rsqrtf(var + 1e-5f);
    }
    __syncthreads();
    float mu = sred[0], rstd = sred2[0];
    #pragma unroll
    for (int j = 0; j < 3; j++) {
        int c = tid + j * 256;
        float v = (j == 0 ? v0 : j == 1 ? v1 : v2);
        float vn = (v - mu) * rstd * g[c] + b[c];
        bf16 h = __float2bfloat16(vn);
        g_anh[(size_t)row * CQ + c] = h;
        g_anl[(size_t)row * CQ + c] = __float2bfloat16(vn - __bfloat162float(h));
    }
}

// ================= weight transpose + split =================
__global__ void k_splitw(const float* w0, const float* w1, const float* w2,
                         const float* w3, const float* w4) {
    int which = blockIdx.y;
    const float* w = (which == 0) ? w0 : (which == 1) ? w1 : (which == 2) ? w2 :
                     (which == 3) ? w3 : w4;
    int idx = blockIdx.x * 256 + threadIdx.x;
    int k = idx / CQ, n = idx - k * CQ;
    float v = w[idx];
    bf16 h = __float2bfloat16(v);
    size_t off = (size_t)which * CQ * CQ + (size_t)n * CQ + k;
    g_wTh[off] = h;
    g_wTl[off] = __float2bfloat16(v - __bfloat162float(h));
}

// ================= pair bias (SIMT, DRAM-bound) =================
#define PB_SMEM_FLOATS (2*256*32 + 2048 + 32)
__global__ __launch_bounds__(256, 2)
void k_pair_bias(const float* __restrict__ z, const float* __restrict__ gz,
                 const float* __restrict__ bz, const float* __restrict__ wz) {
    extern __shared__ float sm[];
    float* zb    = sm;
    float* wps   = sm + 16384;
    float* cs_cb = wps + 2048;

    int tid = threadIdx.x;
    for (int i = tid; i < CZ * NH; i += 256) {
        int c = i >> 4, h = i & 15;
        wps[(c >> 1) * 32 + h * 2 + (c & 1)] = gz[c] * wz[c * NH + h];
    }
    __syncthreads();
    if (tid < 16) {
        float cs = 0.f, cb = 0.f;
        for (int c = 0; c < CZ; c++) {
            cs += wps[(c >> 1) * 32 + tid * 2 + (c & 1)];
            cb += bz[c] * wz[c * NH + tid];
        }
        cs_cb[tid] = cs; cs_cb[16 + tid] = cb;
    }
    __syncthreads();

    int tile = blockIdx.x;
    const float4* zg = (const float4*)(z + (size_t)tile * 256 * CZ);

    int srow[8], sf[8];
    #pragma unroll
    for (int j = 0; j < 8; j++) { int i = tid + j * 256; srow[j] = i >> 3; sf[j] = i & 7; }

    float4 pre[8];
    #pragma unroll
    for (int j = 0; j < 8; j++)
        pre[j] = zg[(size_t)srow[j] * 32 + sf[j]];

    ULL acc[NH];
    #pragma unroll
    for (int h = 0; h < NH; h++) acc[h] = 0ULL;
    ULL sum2 = 0ULL, ss2 = 0ULL;

    for (int c = 0; c < 4; c++) {
        float* buf = zb + (c & 1) * 8192;
        #pragma unroll
        for (int j = 0; j < 8; j++)
            *(float4*)(buf + srow[j] * 32 + ((sf[j] + srow[j]) & 7) * 4) = pre[j];
        __syncthreads();
        if (c < 3) {
            #pragma unroll
            for (int j = 0; j < 8; j++)
                pre[j] = zg[(size_t)srow[j] * 32 + (c + 1) * 8 + sf[j]];
        }
        #pragma unroll
        for (int j = 0; j < 8; j++) {
            int pos = (j + tid) & 7;
            float4 zv = *(const float4*)(buf + tid * 32 + pos * 4);
            ULL z01 = ((const ULL*)&zv)[0];
            ULL z23 = ((const ULL*)&zv)[1];
            sum2 = add2(sum2, add2(z01, z23));
            ss2  = fma2(z01, z01, fma2(z23, z23, ss2));
            int p0 = c * 16 + 2 * j;
            const float4* w0 = (const float4*)(wps + p0 * 32);
            const float4* w1 = (const float4*)(wps + p0 * 32 + 32);
            #pragma unroll
            for (int h2 = 0; h2 < 8; h2++) {
                float4 wa = w0[h2];
                float4 wb = w1[h2];
                acc[2*h2]     = fma2(z01, ((const ULL*)&wa)[0], acc[2*h2]);
                acc[2*h2 + 1] = fma2(z01, ((const ULL*)&wa)[1], acc[2*h2 + 1]);
                acc[2*h2]     = fma2(z23, ((const ULL*)&wb)[0], acc[2*h2]);
                acc[2*h2 + 1] = fma2(z23, ((const ULL*)&wb)[1], acc[2*h2 + 1]);
            }
        }
        __syncthreads();
    }

    float sum = lo2(sum2) + hi2(sum2);
    float ss  = lo2(ss2)  + hi2(ss2);
    float mu  = sum * (1.0f / CZ);
    float var = ss * (1.0f / CZ) - mu * mu;
    float rstd = rsqrtf(var + 1e-5f);

    float* outs = zb;
    #pragma unroll
    for (int h = 0; h < NH; h++) {
        float d = lo2(acc[h]) + hi2(acc[h]);
        outs[h * 256 + tid] = rstd * (d - mu * cs_cb[h]) + cs_cb[16 + h];
    }
    __syncthreads();
    #pragma unroll
    for (int it = 0; it < 4; it++) {
        int idx = tid + it * 256;
        int h = idx >> 6, j4 = idx & 63;
        float4 v = *(const float4*)(outs + h * 256 + j4 * 4);
        *(float4*)(g_bias + ((size_t)h << 20) + (size_t)tile * 256 + j4 * 4) = v;
    }
}

// ================= bf16x3 mma.sync GEMM core, 2-stage cp.async pipeline =================
#define ASTR 40
#define ST_AL 10240u
#define ST_BH 20480u
#define ST_BL 25600u
#define STAGE_BYTES 30720u
#define GEMM_SMEM (2 * STAGE_BYTES)

__device__ __forceinline__ void stage_chunk(
    const bf16* __restrict__ Ah, const bf16* __restrict__ Al, int lda,
    const bf16* __restrict__ Bh, const bf16* __restrict__ Bl, int ldb, int nrealB,
    int k0, int Kreal, uint32_t sb)
{
    int tid = threadIdx.x;
    #pragma unroll
    for (int j = 0; j < 2; j++) {
        int i = tid + j * 256;
        int r = i >> 2, g = i & 3, k = k0 + g * 8;
        bool p = (k < Kreal);
        const bf16* sa = p ? (Ah + (size_t)r * lda + k) : Ah;
        const bf16* sl = p ? (Al + (size_t)r * lda + k) : Al;
        uint32_t doff = (uint32_t)(r * ASTR + g * 8) * 2;
        cpa16(sb + doff, sa, p);
        cpa16(sb + ST_AL + doff, sl, p);
    }
    {
        int r = tid >> 2, g = tid & 3, k = k0 + g * 8;
        bool p = (r < nrealB) && (k < Kreal);
        const bf16* sbh = p ? (Bh + (size_t)r * ldb + k) : Bh;
        const bf16* sbl = p ? (Bl + (size_t)r * ldb + k) : Bl;
        uint32_t doff = (uint32_t)(r * ASTR + g * 8) * 2;
        cpa16(sb + ST_BH + doff, sbh, p);
        cpa16(sb + ST_BL + doff, sbl, p);
    }
    CP_COMMIT();
}

__device__ __forceinline__ void gemm_core(
    const bf16* __restrict__ Ah, const bf16* __restrict__ Al, int lda,
    const bf16* __restrict__ Bh, const bf16* __restrict__ Bl, int ldb, int nrealB,
    int Kreal, int nchunks, uint32_t sbase, float acc[2][4][4])
{
    int lane = threadIdx.x & 31, wid = threadIdx.x >> 5;
    int wm = wid & 3, wn = wid >> 2;
    #pragma unroll
    for (int f = 0; f < 2; f++)
        #pragma unroll
        for (int nf = 0; nf < 4; nf++)
            #pragma unroll
            for (int i = 0; i < 4; i++) acc[f][nf][i] = 0.f;

    int sub = lane >> 3, rin = lane & 7;
    int rowoff = ((sub & 1) << 3) + rin;
    int koff = (sub >> 1) << 3;

    stage_chunk(Ah, Al, lda, Bh, Bl, ldb, nrealB, 0, Kreal, sbase);

    for (int c = 0; c < nchunks; c++) {
        uint32_t sb = sbase + (uint32_t)(c & 1) * STAGE_BYTES;
        if (c + 1 < nchunks) {
            stage_chunk(Ah, Al, lda, Bh, Bl, ldb, nrealB, (c + 1) * 32, Kreal,
                        sbase + (uint32_t)((c + 1) & 1) * STAGE_BYTES);
            CP_WAIT(1);
        } else {
            CP_WAIT(0);
        }
        __syncthreads();

        #pragma unroll
        for (int s = 0; s < 2; s++) {
            uint32_t ah[2][4], al[2][4], bh[2][4], bl[2][4];
            #pragma unroll
            for (int f = 0; f < 2; f++) {
                uint32_t off = (uint32_t)((wm * 32 + f * 16 + rowoff) * ASTR + s * 16 + koff) * 2;
                ldsm4(ah[f], sb + off);
                ldsm4(al[f], sb + ST_AL + off);
            }
            #pragma unroll
            for (int g2 = 0; g2 < 2; g2++) {
                uint32_t off = (uint32_t)((wn * 32 + g2 * 16 + rowoff) * ASTR + s * 16 + koff) * 2;
                ldsm4(bh[g2], sb + ST_BH + off);
                ldsm4(bl[g2], sb + ST_BL + off);
            }
            #pragma unroll
            for (int f = 0; f < 2; f++)
                #pragma unroll
                for (int nf = 0; nf < 4; nf++) {
                    int g2 = nf >> 1, o = nf & 1;
                    mma16816(acc[f][nf], ah[f][0], ah[f][1], ah[f][2], ah[f][3],
                             bh[g2][o], bh[g2][2 + o]);
                    mma16816(acc[f][nf], ah[f][0], ah[f][1], ah[f][2], ah[f][3],
                             bl[g2][o], bl[g2][2 + o]);
                    mma16816(acc[f][nf], al[f][0], al[f][1], al[f][2], al[f][3],
                             bh[g2][o], bh[g2][2 + o]);
                }
        }
        __syncthreads();
    }
}

#define GEMM_SHARED \
    extern __shared__ char dsm[]; \
    uint32_t sbase = s2u(dsm); \
    float acc[2][4][4]; \
    int lane = threadIdx.x & 31, wid = threadIdx.x >> 5; \
    int wm = wid & 3, wn = wid >> 2; \
    int erow = wm * 32 + (lane >> 2); \
    int ecol = wn * 32 + (lane & 3) * 2;

// ---- QKVG ----
__global__ __launch_bounds__(256)
void k_gemm_qkvg(const float* __restrict__ bg) {
    GEMM_SHARED;
    int mode = blockIdx.z;
    int row0 = blockIdx.y * 128, n0 = blockIdx.x * 64;
    const bf16* Bh = g_wTh + (size_t)mode * CQ * CQ + (size_t)n0 * CQ;
    const bf16* Bl = g_wTl + (size_t)mode * CQ * CQ + (size_t)n0 * CQ;
    gemm_core(g_anh + (size_t)row0 * CQ, g_anl + (size_t)row0 * CQ, CQ,
              Bh, Bl, CQ, 64, CQ, CQ / 32, sbase, acc);
    #pragma unroll
    for (int f = 0; f < 2; f++)
        #pragma unroll
        for (int nf = 0; nf < 4; nf++)
            #pragma unroll
            for (int i = 0; i < 4; i++) {
                int row = row0 + erow + f * 16 + (i >> 1) * 8;
                int col = n0 + ecol + nf * 8 + (i & 1);
                float v = acc[f][nf][i];
                int h = col / HD, d = col - h * HD;
                if (mode == 0) {
                    float q = v * QSCALE;
                    bf16 hh = __float2bfloat16(q);
                    g_qh[((size_t)h * NTOK + row) * HD + d] = hh;
                    g_ql[((size_t)h * NTOK + row) * HD + d] = __float2bfloat16(q - __bfloat162float(hh));
                } else if (mode == 1) {
                    bf16 hh = __float2bfloat16(v);
                    g_kh[((size_t)h * NTOK + row) * HD + d] = hh;
                    g_kl[((size_t)h * NTOK + row) * HD + d] = __float2bfloat16(v - __bfloat162float(hh));
                } else if (mode == 2) {
                    bf16 hh = __float2bfloat16(v);
                    g_vth[((size_t)h * HD + d) * NTOK + row] = hh;
                    g_vtl[((size_t)h * HD + d) * NTOK + row] = __float2bfloat16(v - __bfloat162float(hh));
                } else {
                    g_gate[(size_t)row * HDQ + col] = 1.f / (1.f + __expf(-(v + bg[col])));
                }
            }
}

// ================= flash attention on mma.sync =================
// CTA: 128 threads (4 warps), 64 q-rows of one head. Warp = 16 rows.
// smem: Qh 7168 | Ql 7168 | mask 4096 | 2 x (Kh 7168 | Kl 7168 | Vh 6912 | Vl 6912)
#define FL_QL   7168u
#define FL_MSK  14336u
#define FL_BUF0 18432u
#define FL_KL   7168u
#define FL_VH   14336u
#define FL_VL   21248u
#define FL_BUF_BYTES 28160u
#define FL_SMEM (FL_BUF0 + 2 * FL_BUF_BYTES)   // 74752

__device__ __forceinline__ void flash_stage(int h, int c, uint32_t kb) {
    int tid = threadIdx.x;
    // K chunk: 64 rows (tok) x 48 (d), stride 56 bf16
    #pragma unroll
    for (int it = 0; it < 3; it++) {
        int i = tid + it * 128;
        int r = i / 6, kk = i - r * 6;
        const bf16* sh = g_kh + ((size_t)h * NTOK + c * 64 + r) * HD + kk * 8;
        const bf16* sl = g_kl + ((size_t)h * NTOK + c * 64 + r) * HD + kk * 8;
        uint32_t d = kb + (uint32_t)(r * 56 + kk * 8) * 2;
        cpa16(d, sh, true);
        cpa16(d + FL_KL, sl, true);
    }
    // V chunk: 48 rows (d) x 64 (tok), stride 72 bf16
    #pragma unroll
    for (int it = 0; it < 3; it++) {
        int i = tid + it * 128;
        int r = i >> 3, kk = i & 7;
        const bf16* sh = g_vth + ((size_t)h * HD + r) * NTOK + c * 64 + kk * 8;
        const bf16* sl = g_vtl + ((size_t)h * HD + r) * NTOK + c * 64 + kk * 8;
        uint32_t d = kb + FL_VH + (uint32_t)(r * 72 + kk * 8) * 2;
        cpa16(d, sh, true);
        cpa16(d + (FL_VL - FL_VH), sl, true);
    }
    CP_COMMIT();
}

__global__ __launch_bounds__(128)
void k_flash(const float* __restrict__ mask) {
    extern __shared__ char dsm[];
    uint32_t sb = s2u(dsm);
    float* sMask = (float*)(dsm + FL_MSK);
    int h = blockIdx.y, qt = blockIdx.x, tid = threadIdx.x;
    int lane = tid & 31, w = tid >> 5;
    int row0 = qt * 64;
    int r = lane >> 2, cq = lane & 3;
    int sub = lane >> 3, rin = lane & 7;
    int rowoff = ((sub & 1) << 3) + rin;
    int koff = (sub >> 1) << 3;

    for (int i = tid; i < NTOK; i += 128) sMask[i] = mask[i];

    // stage Q (committed with chunk 0)
    #pragma unroll
    for (int it = 0; it < 3; it++) {
        int i = tid + it * 128;
        int rr = i / 6, kk = i - rr * 6;
        const bf16* sh = g_qh + ((size_t)h * NTOK + row0 + rr) * HD + kk * 8;
        const bf16* sl = g_ql + ((size_t)h * NTOK + row0 + rr) * HD + kk * 8;
        uint32_t d = (uint32_t)(rr * 56 + kk * 8) * 2;
        cpa16(sb + d, sh, true);
        cpa16(sb + FL_QL + d, sl, true);
    }
    flash_stage(h, 0, sb + FL_BUF0);
    flash_stage(h, 1, sb + FL_BUF0 + FL_BUF_BYTES);

    uint32_t qh[3][4], ql[3][4];
    float m0 = -1e30f, m1 = -1e30f, l0 = 0.f, l1 = 0.f;
    float oacc[6][4];
    #pragma unroll
    for (int nf = 0; nf < 6; nf++)
        #pragma unroll
        for (int i = 0; i < 4; i++) oacc[nf][i] = 0.f;

    int rg0 = row0 + w * 16 + r, rg1 = rg0 + 8;
    const float* bb = g_bias + ((size_t)h << 20);

    for (int c = 0; c < 16; c++) {
        if (c < 15) { CP_WAIT(1); } else { CP_WAIT(0); }
        __syncthreads();
        if (c == 0) {
            #pragma unroll
            for (int s = 0; s < 3; s++) {
                uint32_t off = (uint32_t)((w * 16 + rowoff) * 56 + s * 16 + koff) * 2;
                ldsm4(qh[s], sb + off);
                ldsm4(ql[s], sb + FL_QL + off);
            }
        }
        uint32_t kb = sb + FL_BUF0 + (uint32_t)(c & 1) * FL_BUF_BYTES;

        // ---- S = Q K^T (bf16x3) ----
        float sacc[8][4];
        #pragma unroll
        for (int nf = 0; nf < 8; nf++)
            #pragma unroll
            for (int i = 0; i < 4; i++) sacc[nf][i] = 0.f;
        #pragma unroll
        for (int s = 0; s < 3; s++) {
            #pragma unroll
            for (int g = 0; g < 4; g++) {
                uint32_t kfh[4], kfl[4];
                uint32_t off = (uint32_t)((g * 16 + rowoff) * 56 + s * 16 + koff) * 2;
                ldsm4(kfh, kb + off);
                ldsm4(kfl, kb + FL_KL + off);
                #pragma unroll
                for (int o = 0; o < 2; o++) {
                    int nf = g * 2 + o;
                    mma16816(sacc[nf], qh[s][0], qh[s][1], qh[s][2], qh[s][3], kfh[o], kfh[2 + o]);
                    mma16816(sacc[nf], qh[s][0], qh[s][1], qh[s][2], qh[s][3], kfl[o], kfl[2 + o]);
                    mma16816(sacc[nf], ql[s][0], ql[s][1], ql[s][2], ql[s][3], kfh[o], kfh[2 + o]);
                }
            }
        }

        // ---- bias + mask + online softmax ----
        float mr0 = sMask[rg0], mr1 = sMask[rg1];
        float mn0 = m0, mn1 = m1;
        #pragma unroll
        for (int nf = 0; nf < 8; nf++) {
            int col = c * 64 + nf * 8 + cq * 2;
            float2 b0 = *(const float2*)(bb + (size_t)rg0 * NTOK + col);
            float2 b1 = *(const float2*)(bb + (size_t)rg1 * NTOK + col);
            float mc0 = sMask[col], mc1 = sMask[col + 1];
            sacc[nf][0] += b0.x + 1e9f * (mr0 * mc0 - 1.f);
            sacc[nf][1] += b0.y + 1e9f * (mr0 * mc1 - 1.f);
            sacc[nf][2] += b1.x + 1e9f * (mr1 * mc0 - 1.f);
            sacc[nf][3] += b1.y + 1e9f * (mr1 * mc1 - 1.f);
            mn0 = fmaxf(mn0, fmaxf(sacc[nf][0], sacc[nf][1]));
            mn1 = fmaxf(mn1, fmaxf(sacc[nf][2], sacc[nf][3]));
        }
        mn0 = fmaxf(mn0, __shfl_xor_sync(0xffffffffu, mn0, 1));
        mn0 = fmaxf(mn0, __shfl_xor_sync(0xffffffffu, mn0, 2));
        mn1 = fmaxf(mn1, __shfl_xor_sync(0xffffffffu, mn1, 1));
        mn1 = fmaxf(mn1, __shfl_xor_sync(0xffffffffu, mn1, 2));
        float sc0 = __expf(m0 - mn0), sc1 = __expf(m1 - mn1);
        m0 = mn0; m1 = mn1;

        float ps0 = 0.f, ps1 = 0.f;
        #pragma unroll
        for (int nf = 0; nf < 8; nf++) {
            sacc[nf][0] = __expf(sacc[nf][0] - m0);
            sacc[nf][1] = __expf(sacc[nf][1] - m0);
            sacc[nf][2] = __expf(sacc[nf][2] - m1);
            sacc[nf][3] = __expf(sacc[nf][3] - m1);
            ps0 += sacc[nf][0] + sacc[nf][1];
            ps1 += sacc[nf][2] + sacc[nf][3];
        }
        ps0 += __shfl_xor_sync(0xffffffffu, ps0, 1);
        ps0 += __shfl_xor_sync(0xffffffffu, ps0, 2);
        ps1 += __shfl_xor_sync(0xffffffffu, ps1, 1);
        ps1 += __shfl_xor_sync(0xffffffffu, ps1, 2);
        l0 = l0 * sc0 + ps0;
        l1 = l1 * sc1 + ps1;

        // rescale O
        #pragma unroll
        for (int nf = 0; nf < 6; nf++) {
            oacc[nf][0] *= sc0; oacc[nf][1] *= sc0;
            oacc[nf][2] *= sc1; oacc[nf][3] *= sc1;
        }

        // ---- pack P fragments (registers only) ----
        uint32_t paH[4][4], paL[4][4];
        #pragma unroll
        for (int s = 0; s < 4; s++) {
            int ne = 2 * s, no = 2 * s + 1;
            bf16 he0 = __float2bfloat16(sacc[ne][0]), he1 = __float2bfloat16(sacc[ne][1]);
            bf16 he2 = __float2bfloat16(sacc[ne][2]), he3 = __float2bfloat16(sacc[ne][3]);
            bf16 ho0 = __float2bfloat16(sacc[no][0]), ho1 = __float2bfloat16(sacc[no][1]);
            bf16 ho2 = __float2bfloat16(sacc[no][2]), ho3 = __float2bfloat16(sacc[no][3]);
            paH[s][0] = pkb(he0, he1);
            paH[s][1] = pkb(he2, he3);
            paH[s][2] = pkb(ho0, ho1);
            paH[s][3] = pkb(ho2, ho3);
            paL[s][0] = pkb(__float2bfloat16(sacc[ne][0] - __bfloat162float(he0)),
                            __float2bfloat16(sacc[ne][1] - __bfloat162float(he1)));
            paL[s][1] = pkb(__float2bfloat16(sacc[ne][2] - __bfloat162float(he2)),
                            __float2bfloat16(sacc[ne][3] - __bfloat162float(he3)));
            paL[s][2] = pkb(__float2bfloat16(sacc[no][0] - __bfloat162float(ho0)),
                            __float2bfloat16(sacc[no][1] - __bfloat162float(ho1)));
            paL[s][3] = pkb(__float2bfloat16(sacc[no][2] - __bfloat162float(ho2)),
                            __float2bfloat16(sacc[no][3] - __bfloat162float(ho3)));
        }

        // ---- O += P @ V (bf16x3) ----
        #pragma unroll
        for (int s = 0; s < 4; s++) {
            #pragma unroll
            for (int g = 0; g < 3; g++) {
                uint32_t vfh[4], vfl[4];
                uint32_t off = (uint32_t)((g * 16 + rowoff) * 72 + s * 16 + koff) * 2;
                ldsm4(vfh, kb + FL_VH + off);
                ldsm4(vfl, kb + FL_VL + off);
                #pragma unroll
                for (int o = 0; o < 2; o++) {
                    int nf = g * 2 + o;
                    mma16816(oacc[nf], paH[s][0], paH[s][1], paH[s][2], paH[s][3], vfh[o], vfh[2 + o]);
                    mma16816(oacc[nf], paH[s][0], paH[s][1], paH[s][2], paH[s][3], vfl[o], vfl[2 + o]);
                    mma16816(oacc[nf], paL[s][0], paL[s][1], paL[s][2], paL[s][3], vfh[o], vfh[2 + o]);
                }
            }
        }

        __syncthreads();
        if (c + 2 < 16)
            flash_stage(h, c + 2, sb + FL_BUF0 + (uint32_t)(c & 1) * FL_BUF_BYTES);
    }

    // ---- epilogue: normalize, gate, split-store ----
    float inv0 = 1.f / l0, inv1 = 1.f / l1;
    #pragma unroll
    for (int nf = 0; nf < 6; nf++) {
        int col = h * HD + nf * 8 + cq * 2;
        size_t i0 = (size_t)rg0 * HDQ + col, i1 = (size_t)rg1 * HDQ + col;
        float2 gt0 = *(const float2*)(g_gate + i0);
        float2 gt1 = *(const float2*)(g_gate + i1);
        float o00 = oacc[nf][0] * inv0 * gt0.x;
        float o01 = oacc[nf][1] * inv0 * gt0.y;
        float o10 = oacc[nf][2] * inv1 * gt1.x;
        float o11 = oacc[nf][3] * inv1 * gt1.y;
        bf16 b00 = __float2bfloat16(o00), b01 = __float2bfloat16(o01);
        bf16 b10 = __float2bfloat16(o10), b11 = __float2bfloat16(o11);
        *(uint32_t*)(g_ogh + i0) = pkb(b00, b01);
        *(uint32_t*)(g_ogh + i1) = pkb(b10, b11);
        *(uint32_t*)(g_ogl + i0) = pkb(__float2bfloat16(o00 - __bfloat162float(b00)),
                                       __float2bfloat16(o01 - __bfloat162float(b01)));
        *(uint32_t*)(g_ogl + i1) = pkb(__float2bfloat16(o10 - __bfloat162float(b10)),
                                       __float2bfloat16(o11 - __bfloat162float(b11)));
    }
}

// ---- out projection ----
__global__ __launch_bounds__(256)
void k_gemm_out(const float* __restrict__ bo, float* __restrict__ out) {
    GEMM_SHARED;
    int row0 = blockIdx.y * 128, n0 = blockIdx.x * 64;
    const bf16* Bh = g_wTh + 4ull * CQ * CQ + (size_t)n0 * CQ;
    const bf16* Bl = g_wTl + 4ull * CQ * CQ + (size_t)n0 * CQ;
    gemm_core(g_ogh + (size_t)row0 * CQ, g_ogl + (size_t)row0 * CQ, CQ,
              Bh, Bl, CQ, 64, CQ, CQ / 32, sbase, acc);
    #pragma unroll
    for (int f = 0; f < 2; f++)
        #pragma unroll
        for (int nf = 0; nf < 4; nf++)
            #pragma unroll
            for (int i = 0; i < 4; i++) {
                int row = row0 + erow + f * 16 + (i >> 1) * 8;
                int col = n0 + ecol + nf * 8 + (i & 1);
                out[(size_t)row * CQ + col] = acc[f][nf][i] + __ldg(bo + col);
            }
}

// ================= launch =================
extern "C" void kernel_launch(void* const* d_in, const int* in_sizes, int n_in,
                              void* d_out, int out_size) {
    const float* a    = (const float*)d_in[0];
    const float* z    = (const float*)d_in[1];
    const float* mask = (const float*)d_in[2];
    const float* ga   = (const float*)d_in[3];
    const float* ba   = (const float*)d_in[4];
    const float* gz   = (const float*)d_in[5];
    const float* bz   = (const float*)d_in[6];
    const float* wz   = (const float*)d_in[7];
    const float* wq   = (const float*)d_in[8];
    const float* wk   = (const float*)d_in[9];
    const float* wv   = (const float*)d_in[10];
    const float* wg   = (const float*)d_in[11];
    const float* bg   = (const float*)d_in[12];
    const float* wo   = (const float*)d_in[13];
    const float* bo   = (const float*)d_in[14];
    float* out = (float*)d_out;

    cudaFuncSetAttribute(k_pair_bias, cudaFuncAttributeMaxDynamicSharedMemorySize, PB_SMEM_FLOATS * 4);
    cudaFuncSetAttribute(k_gemm_qkvg, cudaFuncAttributeMaxDynamicSharedMemorySize, GEMM_SMEM);
    cudaFuncSetAttribute(k_flash,     cudaFuncAttributeMaxDynamicSharedMemorySize, FL_SMEM);
    cudaFuncSetAttribute(k_gemm_out,  cudaFuncAttributeMaxDynamicSharedMemorySize, GEMM_SMEM);

    cudaStream_t s1;
    cudaEvent_t e_fork, e_join;
    cudaStreamCreateWithFlags(&s1, cudaStreamNonBlocking);
    cudaEventCreateWithFlags(&e_fork, cudaEventDisableTiming);
    cudaEventCreateWithFlags(&e_join, cudaEventDisableTiming);

    cudaEventRecord(e_fork, 0);
    cudaStreamWaitEvent(s1, e_fork, 0);

    k_pair_bias<<<4096, 256, PB_SMEM_FLOATS * 4, s1>>>(z, gz, bz, wz);
    cudaEventRecord(e_join, s1);

    k_ln_a<<<1024, 256>>>(a, ga, ba);
    k_splitw<<<dim3(CQ * CQ / 256, 5), 256>>>(wq, wk, wv, wg, wo);
    k_gemm_qkvg<<<dim3(12, 8, 4), 256, GEMM_SMEM>>>(bg);

    cudaStreamWaitEvent(0, e_join, 0);

    k_flash<<<dim3(16, NH), 128, FL_SMEM>>>(mask);
    k_gemm_out<<<dim3(12, 8), 256, GEMM_SMEM>>>(bo, out);
}